// round 4
// baseline (speedup 1.0000x reference)
#include <cuda_runtime.h>
#include <cstdint>
#include <cstring>

#define KK 16
#define FF 32
#define NT 64
#define NTHREADS 256
#define NWARP (NTHREADS/32)

__device__ __forceinline__ float warpsum(float v){
  #pragma unroll
  for (int o = 16; o > 0; o >>= 1) v += __shfl_xor_sync(0xffffffffu, v, o);
  return v;
}

// sum within aligned 8-lane groups
__device__ __forceinline__ float grp8sum(float v){
  v += __shfl_xor_sync(0xffffffffu, v, 1);
  v += __shfl_xor_sync(0xffffffffu, v, 2);
  v += __shfl_xor_sync(0xffffffffu, v, 4);
  return v;
}

// packed f32x2 FMA (sm_100+; emits FFMA2 — not reachable from C++)
__device__ __forceinline__ unsigned long long ffma2(unsigned long long a,
                                                    unsigned long long b,
                                                    unsigned long long c){
  unsigned long long d;
  asm("fma.rn.f32x2 %0, %1, %2, %3;" : "=l"(d) : "l"(a), "l"(b), "l"(c));
  return d;
}

__device__ __forceinline__ float2 unpack2(unsigned long long a){
  float2 f;
  asm("mov.b64 {%0, %1}, %2;" : "=f"(f.x), "=f"(f.y) : "l"(a));
  return f;
}

// int64 vs int32 index array detection (node ids < 2^31)
__device__ __forceinline__ int is64_flag(const void* p){
  const unsigned int* u = (const unsigned int*)p;
  return ((u[1] | u[3] | u[5] | u[7]) == 0u) ? 1 : 0;
}
__device__ __forceinline__ long long ldidx(const void* p, long long i, int is64){
  if (is64) return ((const long long*)p)[i];
  return (long long)((const int*)p)[i];
}

template<int DEG>
__global__ void __launch_bounds__(NTHREADS, 4) score_kernel(
    const float* __restrict__ x,
    const void* __restrict__ sel,
    const void* __restrict__ nei,
    const float* __restrict__ Wf,
    const float* __restrict__ Wn,
    float* __restrict__ out,
    int Nd)
{
  constexpr int RPG = 1 + DEG;       // rows (focal + neighbors) per node
  constexpr int L   = RPG * FF;      // extended feature length
  constexpr int LP  = L + 4;         // padded stride (16B-aligned, bank-skewed)

  extern __shared__ float smem[];
  float* Xs = smem;                       // NT * LP
  float* Ws = smem + NT * LP;             // KK * LP
  int*   Is = (int*)(smem + NT * LP + KK * LP);  // NT node ids

  const int tid  = threadIdx.x;
  const int w    = tid >> 5;
  const int lane = tid & 31;
  const int tile = blockIdx.x * NT;
  const int count = min(NT, Nd - tile);
  const int s64 = is64_flag(sel);
  const int n64 = is64_flag(nei);

  // ---- Phase 0: normalize weights into SMEM (1/DEG folded into neighbor rows)
  {
    constexpr int RW = KK * RPG;
    for (int r = w; r < RW; r += NWARP){
      const int k = r / RPG, s = r % RPG;
      float v = (s == 0) ? Wf[k * FF + lane]
                         : Wn[(k * DEG + (s - 1)) * FF + lane];
      const float ss = warpsum(v * v);
      float sc = rsqrtf(ss);
      if (s) sc *= (1.0f / DEG);
      Ws[k * LP + s * FF + lane] = v * sc;
    }
  }

  // ---- Phase 1: gather + L2-normalize node rows into SMEM.
  // A "group" = 4 consecutive rows, covered by one LDG.128 per lane
  // (8 lanes x float4 per row). 4 groups pipelined per warp -> MLP>=4.
  {
    constexpr int G = (NT * RPG) / 4;     // groups per block (32..80)
    const int c  = lane & 7;              // float4 slot within row
    const int rg = lane >> 3;             // row within group

    #pragma unroll 1
    for (int g0 = w; g0 < G; g0 += NWARP * 4){
      long long gi[4]; int nn[4], ss_[4]; bool val[4];
      #pragma unroll
      for (int u = 0; u < 4; u++){
        const int g = g0 + u * NWARP;
        const int r = g * 4 + rg;
        nn[u] = r / RPG; ss_[u] = r - nn[u] * RPG;
        val[u] = (g < G) && (nn[u] < count);
        gi[u] = 0;
        if (val[u]){
          gi[u] = (ss_[u] == 0) ? ldidx(sel, tile + nn[u], s64)
                                : ldidx(nei, (long long)(tile + nn[u]) * DEG + (ss_[u] - 1), n64);
        }
      }
      float4 v[4];
      #pragma unroll
      for (int u = 0; u < 4; u++){
        v[u] = val[u] ? *(const float4*)&x[gi[u] * FF + c * 4]
                      : make_float4(0.f, 0.f, 0.f, 0.f);
      }
      #pragma unroll
      for (int u = 0; u < 4; u++){
        const float ssq = grp8sum(v[u].x * v[u].x + v[u].y * v[u].y
                                + v[u].z * v[u].z + v[u].w * v[u].w);
        const float sc = (ssq > 0.0f) ? rsqrtf(ssq) : 0.0f;
        if (val[u]){
          float4 o; o.x = v[u].x * sc; o.y = v[u].y * sc; o.z = v[u].z * sc; o.w = v[u].w * sc;
          *(float4*)&Xs[nn[u] * LP + ss_[u] * FF + c * 4] = o;
          if (ss_[u] == 0 && c == 0) Is[nn[u]] = (int)gi[u];
        }
      }
    }
  }
  __syncthreads();

  // ---- Phase 2a: zero-fill the 48 non-score columns of each node's output row.
  {
    const int col = lane * 4 + ((lane * 4 >= 16 * (DEG - 1)) ? 16 : 0);
    const bool wr = (lane < 12);
    const float4 z = make_float4(0.f, 0.f, 0.f, 0.f);
    for (int n = w; n < count; n += NWARP){
      const long long node = Is[n];
      if (wr) *(float4*)&out[node * 64 + col] = z;
    }
  }

  // ---- Phase 2b: register-tiled GEMM with packed f32x2 FMA.
  // 256 threads: thread = 2 nodes (ng) x 2 kernels (kg).
  {
    const int kg = tid & 7;     // 8 k-groups of 2
    const int ng = tid >> 3;    // 32 node-groups of 2
    unsigned long long acc[2][2];
    #pragma unroll
    for (int i = 0; i < 2; i++)
      #pragma unroll
      for (int j = 0; j < 2; j++) acc[i][j] = 0ULL;

    const float* xb = Xs + (ng * 2) * LP;
    const float* wb = Ws + (kg * 2) * LP;

    #pragma unroll 4
    for (int ff = 0; ff < L; ff += 4){
      ulonglong2 xv[2], wv[2];
      #pragma unroll
      for (int i = 0; i < 2; i++)
        xv[i] = *(const ulonglong2*)(xb + i * LP + ff);
      #pragma unroll
      for (int j = 0; j < 2; j++)
        wv[j] = *(const ulonglong2*)(wb + j * LP + ff);
      #pragma unroll
      for (int i = 0; i < 2; i++){
        #pragma unroll
        for (int j = 0; j < 2; j++){
          acc[i][j] = ffma2(xv[i].x, wv[j].x, acc[i][j]);
          acc[i][j] = ffma2(xv[i].y, wv[j].y, acc[i][j]);
        }
      }
    }

    // scatter scores: per node a float2 at columns [16*(DEG-1)+kg*2, +2)
    #pragma unroll
    for (int i = 0; i < 2; i++){
      const int n = ng * 2 + i;
      if (n < count){
        const float2 a0 = unpack2(acc[i][0]);
        const float2 a1 = unpack2(acc[i][1]);
        float2 sv; sv.x = a0.x + a0.y; sv.y = a1.x + a1.y;
        const long long node = Is[n];
        *(float2*)&out[node * 64 + (DEG - 1) * 16 + kg * 2] = sv;
      }
    }
  }
}

static inline int smem_bytes(int deg){
  const int LP = (1 + deg) * FF + 4;
  return ((NT + KK) * LP) * (int)sizeof(float) + NT * (int)sizeof(int);
}

extern "C" void kernel_launch(void* const* d_in, const int* in_sizes, int n_in,
                              void* d_out, int out_size)
{
  const float* x = (const float*)d_in[0];
  const void *sel[4], *nei[4];
  const float *Wf[4], *Wn[4];
  int Nd[4];

  if (in_sizes[1] == 512){
    // reference-signature order: x, (Wf,Wn)x4, sel1..4, nei1..4
    for (int d = 0; d < 4; d++){
      Wf[d]  = (const float*)d_in[1 + 2 * d];
      Wn[d]  = (const float*)d_in[2 + 2 * d];
      sel[d] = d_in[9 + d];
      nei[d] = d_in[13 + d];
      Nd[d]  = in_sizes[9 + d];
    }
  } else {
    // setup_inputs dict order: x, then (sel, nei, Wf, Wn) per degree
    int b = 1;
    for (int d = 0; d < 4; d++){
      sel[d] = d_in[b + 0];
      nei[d] = d_in[b + 1];
      Wf[d]  = (const float*)d_in[b + 2];
      Wn[d]  = (const float*)d_in[b + 3];
      Nd[d]  = in_sizes[b + 0];
      b += 4;
    }
  }

  float* out = (float*)d_out;

  cudaFuncSetAttribute(score_kernel<1>, cudaFuncAttributeMaxDynamicSharedMemorySize, smem_bytes(1));
  cudaFuncSetAttribute(score_kernel<2>, cudaFuncAttributeMaxDynamicSharedMemorySize, smem_bytes(2));
  cudaFuncSetAttribute(score_kernel<3>, cudaFuncAttributeMaxDynamicSharedMemorySize, smem_bytes(3));
  cudaFuncSetAttribute(score_kernel<4>, cudaFuncAttributeMaxDynamicSharedMemorySize, smem_bytes(4));

  score_kernel<1><<<(Nd[0] + NT - 1) / NT, NTHREADS, smem_bytes(1)>>>(
      x, sel[0], nei[0], Wf[0], Wn[0], out, Nd[0]);
  score_kernel<2><<<(Nd[1] + NT - 1) / NT, NTHREADS, smem_bytes(2)>>>(
      x, sel[1], nei[1], Wf[1], Wn[1], out, Nd[1]);
  score_kernel<3><<<(Nd[2] + NT - 1) / NT, NTHREADS, smem_bytes(3)>>>(
      x, sel[2], nei[2], Wf[2], Wn[2], out, Nd[2]);
  score_kernel<4><<<(Nd[3] + NT - 1) / NT, NTHREADS, smem_bytes(4)>>>(
      x, sel[3], nei[3], Wf[3], Wn[3], out, Nd[3]);
}

// round 6
// speedup vs baseline: 1.2176x; 1.2176x over previous
#include <cuda_runtime.h>
#include <cstdint>
#include <cstring>

#define KK 16
#define FF 32
#define NT 64
#define NTHREADS 256
#define NWARP (NTHREADS/32)

__device__ __forceinline__ float warpsum(float v){
  #pragma unroll
  for (int o = 16; o > 0; o >>= 1) v += __shfl_xor_sync(0xffffffffu, v, o);
  return v;
}

__device__ __forceinline__ float grp8sum(float v){
  v += __shfl_xor_sync(0xffffffffu, v, 1);
  v += __shfl_xor_sync(0xffffffffu, v, 2);
  v += __shfl_xor_sync(0xffffffffu, v, 4);
  return v;
}

// packed f32x2 ops (sm_100+; FFMA2/FADD2 not reachable from C++)
__device__ __forceinline__ unsigned long long ffma2(unsigned long long a,
                                                    unsigned long long b,
                                                    unsigned long long c){
  unsigned long long d;
  asm("fma.rn.f32x2 %0, %1, %2, %3;" : "=l"(d) : "l"(a), "l"(b), "l"(c));
  return d;
}
__device__ __forceinline__ unsigned long long fadd2(unsigned long long a,
                                                    unsigned long long b){
  unsigned long long d;
  asm("add.rn.f32x2 %0, %1, %2;" : "=l"(d) : "l"(a), "l"(b));
  return d;
}
__device__ __forceinline__ float2 unpack2(unsigned long long a){
  float2 f;
  asm("mov.b64 {%0, %1}, %2;" : "=f"(f.x), "=f"(f.y) : "l"(a));
  return f;
}

// int64 vs int32 index array detection (node ids < 2^31)
__device__ __forceinline__ int is64_flag(const void* p){
  const unsigned int* u = (const unsigned int*)p;
  return ((u[1] | u[3] | u[5] | u[7]) == 0u) ? 1 : 0;
}
__device__ __forceinline__ long long ldidx(const void* p, long long i, int is64){
  if (is64) return ((const long long*)p)[i];
  return (long long)((const int*)p)[i];
}

// DEG: degree; TN x TK: per-thread node x kernel tile; FS: feature-split ways.
// (64/TN)*(16/TK)*FS == 256 threads.
template<int DEG, int TN, int TK, int FS, int MINB>
__global__ void __launch_bounds__(NTHREADS, MINB) score_kernel(
    const float* __restrict__ x,
    const void* __restrict__ sel,
    const void* __restrict__ nei,
    const float* __restrict__ Wf,
    const float* __restrict__ Wn,
    float* __restrict__ out,
    int Nd)
{
  constexpr int RPG = 1 + DEG;       // rows per node (focal + neighbors)
  constexpr int L   = RPG * FF;      // extended feature length
  constexpr int LP  = L + 4;         // padded stride: mult of 4, ==4 (mod 8)

  extern __shared__ float smem[];
  float* Xs = smem;                       // NT * LP
  float* Ws = smem + NT * LP;             // KK * LP
  int*   Is = (int*)(smem + NT * LP + KK * LP);  // NT node ids

  const int tid  = threadIdx.x;
  const int w    = tid >> 5;
  const int lane = tid & 31;
  const int tile = blockIdx.x * NT;
  const int count = min(NT, Nd - tile);
  const int s64 = is64_flag(sel);
  const int n64 = is64_flag(nei);

  // ---- Phase 0: normalize weights into SMEM (1/DEG folded into neighbor rows)
  {
    constexpr int RW = KK * RPG;
    for (int r = w; r < RW; r += NWARP){
      const int k = r / RPG, s = r % RPG;
      float v = (s == 0) ? Wf[k * FF + lane]
                         : Wn[(k * DEG + (s - 1)) * FF + lane];
      const float ss = warpsum(v * v);
      float sc = rsqrtf(ss);
      if (s) sc *= (1.0f / DEG);
      Ws[k * LP + s * FF + lane] = v * sc;
    }
  }

  // ---- Phase 1: gather + L2-normalize node rows into SMEM.
  // group = 4 rows via one LDG.128/lane (8 lanes per row); 4 groups pipelined.
  {
    constexpr int G = (NT * RPG) / 4;
    const int c  = lane & 7;
    const int rg = lane >> 3;

    #pragma unroll 1
    for (int g0 = w; g0 < G; g0 += NWARP * 4){
      long long gi[4]; int nn[4], ss_[4]; bool val[4];
      #pragma unroll
      for (int u = 0; u < 4; u++){
        const int g = g0 + u * NWARP;
        const int r = g * 4 + rg;
        nn[u] = r / RPG; ss_[u] = r - nn[u] * RPG;
        val[u] = (g < G) && (nn[u] < count);
        gi[u] = 0;
        if (val[u]){
          gi[u] = (ss_[u] == 0) ? ldidx(sel, tile + nn[u], s64)
                                : ldidx(nei, (long long)(tile + nn[u]) * DEG + (ss_[u] - 1), n64);
        }
      }
      float4 v[4];
      #pragma unroll
      for (int u = 0; u < 4; u++){
        v[u] = val[u] ? *(const float4*)&x[gi[u] * FF + c * 4]
                      : make_float4(0.f, 0.f, 0.f, 0.f);
      }
      #pragma unroll
      for (int u = 0; u < 4; u++){
        const float ssq = grp8sum(v[u].x * v[u].x + v[u].y * v[u].y
                                + v[u].z * v[u].z + v[u].w * v[u].w);
        const float sc = (ssq > 0.0f) ? rsqrtf(ssq) : 0.0f;
        if (val[u]){
          float4 o; o.x = v[u].x * sc; o.y = v[u].y * sc; o.z = v[u].z * sc; o.w = v[u].w * sc;
          *(float4*)&Xs[nn[u] * LP + ss_[u] * FF + c * 4] = o;
          if (ss_[u] == 0 && c == 0) Is[nn[u]] = (int)gi[u];
        }
      }
    }
  }
  __syncthreads();

  // ---- Phase 2a: zero-fill the 48 non-score columns of each node's output row.
  {
    const int col = lane * 4 + ((lane * 4 >= 16 * (DEG - 1)) ? 16 : 0);
    const bool wr = (lane < 12);
    const float4 z = make_float4(0.f, 0.f, 0.f, 0.f);
    for (int n = w; n < count; n += NWARP){
      const long long node = Is[n];
      if (wr) *(float4*)&out[node * 64 + col] = z;
    }
  }

  // ---- Phase 2b: register-tiled GEMM, f32x2 FMA, feature-split across lanes.
  // lane = [kg][fs][ngl] with NGL=2 ng values per warp-lane-group.
  {
    constexpr int NGL = 2 * TK / FS;          // == 2 for all configs used
    static_assert(NGL == 2, "lane mapping assumes NGL==2");
    const int kg  = lane >> (1 + (FS == 2 ? 1 : 2));   // lane / (FS*NGL)
    const int fs  = (lane >> 1) & (FS - 1);
    const int ng  = (w << 1) | (lane & 1);

    unsigned long long acc[TN][TK];
    #pragma unroll
    for (int i = 0; i < TN; i++)
      #pragma unroll
      for (int j = 0; j < TK; j++) acc[i][j] = 0ULL;

    const float* xb = Xs + (ng * TN) * LP + fs * 4;
    const float* wb = Ws + (kg * TK) * LP + fs * 4;
    constexpr int CHUNKS = L / (4 * FS);

    #pragma unroll
    for (int cidx = 0; cidx < CHUNKS; cidx++){
      const int off = cidx * 4 * FS;
      ulonglong2 xv[TN], wv[TK];
      #pragma unroll
      for (int i = 0; i < TN; i++)
        xv[i] = *(const ulonglong2*)(xb + i * LP + off);
      #pragma unroll
      for (int j = 0; j < TK; j++)
        wv[j] = *(const ulonglong2*)(wb + j * LP + off);
      #pragma unroll
      for (int i = 0; i < TN; i++){
        #pragma unroll
        for (int j = 0; j < TK; j++){
          acc[i][j] = ffma2(xv[i].x, wv[j].x, acc[i][j]);
          acc[i][j] = ffma2(xv[i].y, wv[j].y, acc[i][j]);
        }
      }
    }

    // cross-fs reduction (fs lives in lane bits starting at bit 1)
    #pragma unroll
    for (int mask = 2; mask < 2 * FS; mask <<= 1){
      #pragma unroll
      for (int i = 0; i < TN; i++)
        #pragma unroll
        for (int j = 0; j < TK; j++){
          unsigned long long o = __shfl_xor_sync(0xffffffffu, acc[i][j], mask);
          acc[i][j] = fadd2(acc[i][j], o);
        }
    }

    // fs==0 lanes write TK scores per node at col 16*(DEG-1)+kg*TK
    if (fs == 0){
      #pragma unroll
      for (int i = 0; i < TN; i++){
        const int n = ng * TN + i;
        if (n < count){
          const long long node = Is[n];
          float s[TK];
          #pragma unroll
          for (int j = 0; j < TK; j++){
            const float2 a = unpack2(acc[i][j]);
            s[j] = a.x + a.y;
          }
          float* dst = &out[node * 64 + (DEG - 1) * 16 + kg * TK];
          if (TK == 4){
            float4 v4; v4.x = s[0]; v4.y = s[1]; v4.z = s[2]; v4.w = s[3];
            *(float4*)dst = v4;
          } else {
            float2 v2; v2.x = s[0]; v2.y = s[1];
            *(float2*)dst = v2;
          }
        }
      }
    }
  }
}

static inline int smem_bytes(int deg){
  const int LP = (1 + deg) * FF + 4;
  return ((NT + KK) * LP) * (int)sizeof(float) + NT * (int)sizeof(int);
}

extern "C" void kernel_launch(void* const* d_in, const int* in_sizes, int n_in,
                              void* d_out, int out_size)
{
  const float* x = (const float*)d_in[0];
  const void *sel[4], *nei[4];
  const float *Wf[4], *Wn[4];
  int Nd[4];

  if (in_sizes[1] == 512){
    // reference-signature order: x, (Wf,Wn)x4, sel1..4, nei1..4
    for (int d = 0; d < 4; d++){
      Wf[d]  = (const float*)d_in[1 + 2 * d];
      Wn[d]  = (const float*)d_in[2 + 2 * d];
      sel[d] = d_in[9 + d];
      nei[d] = d_in[13 + d];
      Nd[d]  = in_sizes[9 + d];
    }
  } else {
    // setup_inputs dict order: x, then (sel, nei, Wf, Wn) per degree
    int b = 1;
    for (int d = 0; d < 4; d++){
      sel[d] = d_in[b + 0];
      nei[d] = d_in[b + 1];
      Wf[d]  = (const float*)d_in[b + 2];
      Wn[d]  = (const float*)d_in[b + 3];
      Nd[d]  = in_sizes[b + 0];
      b += 4;
    }
  }

  float* out = (float*)d_out;

  cudaFuncSetAttribute((const void*)score_kernel<1,4,2,2,4>, cudaFuncAttributeMaxDynamicSharedMemorySize, smem_bytes(1));
  cudaFuncSetAttribute((const void*)score_kernel<2,4,2,2,4>, cudaFuncAttributeMaxDynamicSharedMemorySize, smem_bytes(2));
  cudaFuncSetAttribute((const void*)score_kernel<3,4,4,4,3>, cudaFuncAttributeMaxDynamicSharedMemorySize, smem_bytes(3));
  cudaFuncSetAttribute((const void*)score_kernel<4,4,4,4,3>, cudaFuncAttributeMaxDynamicSharedMemorySize, smem_bytes(4));

  score_kernel<1,4,2,2,4><<<(Nd[0] + NT - 1) / NT, NTHREADS, smem_bytes(1)>>>(
      x, sel[0], nei[0], Wf[0], Wn[0], out, Nd[0]);
  score_kernel<2,4,2,2,4><<<(Nd[1] + NT - 1) / NT, NTHREADS, smem_bytes(2)>>>(
      x, sel[1], nei[1], Wf[1], Wn[1], out, Nd[1]);
  score_kernel<3,4,4,4,3><<<(Nd[2] + NT - 1) / NT, NTHREADS, smem_bytes(3)>>>(
      x, sel[2], nei[2], Wf[2], Wn[2], out, Nd[2]);
  score_kernel<4,4,4,4,3><<<(Nd[3] + NT - 1) / NT, NTHREADS, smem_bytes(4)>>>(
      x, sel[3], nei[3], Wf[3], Wn[3], out, Nd[3]);
}

// round 7
// speedup vs baseline: 1.6961x; 1.3930x over previous
#include <cuda_runtime.h>
#include <cstdint>
#include <cstring>

#define KK 16
#define FF 32
#define NT 64
#define NTHREADS 256
#define NWARP (NTHREADS/32)

__device__ __forceinline__ float warpsum(float v){
  #pragma unroll
  for (int o = 16; o > 0; o >>= 1) v += __shfl_xor_sync(0xffffffffu, v, o);
  return v;
}

__device__ __forceinline__ float grp8sum(float v){
  v += __shfl_xor_sync(0xffffffffu, v, 1);
  v += __shfl_xor_sync(0xffffffffu, v, 2);
  v += __shfl_xor_sync(0xffffffffu, v, 4);
  return v;
}

// packed f32x2 ops (sm_100+; FFMA2/FADD2 not reachable from C++)
__device__ __forceinline__ unsigned long long ffma2(unsigned long long a,
                                                    unsigned long long b,
                                                    unsigned long long c){
  unsigned long long d;
  asm("fma.rn.f32x2 %0, %1, %2, %3;" : "=l"(d) : "l"(a), "l"(b), "l"(c));
  return d;
}
__device__ __forceinline__ unsigned long long fadd2(unsigned long long a,
                                                    unsigned long long b){
  unsigned long long d;
  asm("add.rn.f32x2 %0, %1, %2;" : "=l"(d) : "l"(a), "l"(b));
  return d;
}
__device__ __forceinline__ float2 unpack2(unsigned long long a){
  float2 f;
  asm("mov.b64 {%0, %1}, %2;" : "=f"(f.x), "=f"(f.y) : "l"(a));
  return f;
}

__device__ __forceinline__ uint32_t smem_u32(const void* p){
  uint32_t a;
  asm("{ .reg .u64 t; cvta.to.shared.u64 t, %1; cvt.u32.u64 %0, t; }"
      : "=r"(a) : "l"(p));
  return a;
}

__device__ __forceinline__ void cp_async16(uint32_t dst, const void* src){
  asm volatile("cp.async.cg.shared.global [%0], [%1], 16;"
               :: "r"(dst), "l"(src));
}

// int64 vs int32 index array detection (node ids < 2^31)
__device__ __forceinline__ int is64_flag(const void* p){
  const unsigned int* u = (const unsigned int*)p;
  return ((u[1] | u[3] | u[5] | u[7]) == 0u) ? 1 : 0;
}
// 32-bit id fetch regardless of storage width (values < 2^31, little-endian)
__device__ __forceinline__ int ldidx32(const void* p, int i, int is64){
  return is64 ? ((const int*)p)[2 * i] : ((const int*)p)[i];
}

// DEG: degree; TN x TK: per-thread node x kernel tile; FS: feature-split ways.
template<int DEG, int TN, int TK, int FS, int MINB>
__global__ void __launch_bounds__(NTHREADS, MINB) score_kernel(
    const float* __restrict__ x,
    const void* __restrict__ sel,
    const void* __restrict__ nei,
    const float* __restrict__ Wf,
    const float* __restrict__ Wn,
    float* __restrict__ out,
    int Nd)
{
  constexpr int RPG  = 1 + DEG;       // rows per node (focal + neighbors)
  constexpr int L    = RPG * FF;      // extended feature length
  constexpr int LP   = L + 4;         // padded stride: mult of 4 floats (16B), ==4 (mod 8)
  constexpr int RTOT = NT * RPG;      // extended rows per tile

  extern __shared__ float smem[];
  float* Xs = smem;                               // NT * LP
  float* Ws = smem + NT * LP;                     // KK * LP
  int*   Rs = (int*)(smem + NT * LP + KK * LP);   // RTOT row ids (row n*RPG is sel id)

  const int tid  = threadIdx.x;
  const int w    = tid >> 5;
  const int lane = tid & 31;
  const int tile = blockIdx.x * NT;
  const int count = min(NT, Nd - tile);
  const int s64 = is64_flag(sel);
  const int n64 = is64_flag(nei);

  // ---- Phase A: stage all row ids for this tile into SMEM (coalesced).
  {
    #pragma unroll
    for (int r = tid; r < RTOT; r += NTHREADS){
      const int nn = r / RPG, ss = r - nn * RPG;
      int id = 0;
      if (nn < count)
        id = (ss == 0) ? ldidx32(sel, tile + nn, s64)
                       : ldidx32(nei, (tile + nn) * DEG + ss - 1, n64);
      Rs[r] = id;
    }
  }
  __syncthreads();

  // ---- Phase B: fire the whole gather as cp.async (GMEM -> SMEM, no RF).
  // thread t covers slot c = t&7 (16B), rows r = (t>>3) + 32*i.
  {
    const int c  = tid & 7;
    const int rb = tid >> 3;
    constexpr int ITER = RTOT / 32;          // 4..10
    constexpr int DNN = 32 / RPG, DSS = 32 % RPG;
    const uint32_t xs0 = smem_u32(Xs) + (uint32_t)(c * 16);
    int nn = rb / RPG, ss = rb - nn * RPG;
    #pragma unroll
    for (int i = 0; i < ITER; i++){
      if (nn < count){
        const unsigned id = (unsigned)Rs[rb + 32 * i];
        const float* src = x + (size_t)(id * (unsigned)FF) + c * 4;
        const uint32_t dst = xs0 + (uint32_t)((nn * LP + ss * FF) * 4);
        cp_async16(dst, src);
      }
      ss += DSS;
      const int wrap = (ss >= RPG);
      if (wrap) ss -= RPG;
      nn += DNN + wrap;
    }
    asm volatile("cp.async.commit_group;");
  }

  // ---- Phase 0 (overlapped with gather): normalize weights into SMEM.
  {
    constexpr int RW = KK * RPG;
    for (int r = w; r < RW; r += NWARP){
      const int k = r / RPG, s = r % RPG;
      float v = (s == 0) ? Wf[k * FF + lane]
                         : Wn[(k * DEG + (s - 1)) * FF + lane];
      const float ss2 = warpsum(v * v);
      float sc = rsqrtf(ss2);
      if (s) sc *= (1.0f / DEG);
      Ws[k * LP + s * FF + lane] = v * sc;
    }
  }

  asm volatile("cp.async.wait_group 0;" ::: "memory");
  __syncthreads();

  // ---- Phase C: L2-normalize gathered rows in place (LDS -> reduce -> STS).
  {
    constexpr int G = RTOT / 4;          // 4-row groups
    const int c  = lane & 7;
    const int rg = lane >> 3;
    #pragma unroll 1
    for (int g0 = w; g0 < G; g0 += NWARP * 4){
      float4 v[4]; int off[4]; bool val[4];
      #pragma unroll
      for (int u = 0; u < 4; u++){
        const int g = g0 + u * NWARP;
        const int r = g * 4 + rg;
        const int nn = r / RPG, ss = r - nn * RPG;
        val[u] = (g < G) && (nn < count);
        off[u] = nn * LP + ss * FF + c * 4;
        v[u] = val[u] ? *(const float4*)&Xs[off[u]]
                      : make_float4(0.f, 0.f, 0.f, 0.f);
      }
      #pragma unroll
      for (int u = 0; u < 4; u++){
        const float ssq = grp8sum(v[u].x * v[u].x + v[u].y * v[u].y
                                + v[u].z * v[u].z + v[u].w * v[u].w);
        const float sc = (ssq > 0.0f) ? rsqrtf(ssq) : 0.0f;
        if (val[u]){
          float4 o; o.x = v[u].x * sc; o.y = v[u].y * sc; o.z = v[u].z * sc; o.w = v[u].w * sc;
          *(float4*)&Xs[off[u]] = o;
        }
      }
    }
  }
  __syncthreads();

  // ---- Phase 2a: zero-fill the 48 non-score columns of each node's output row.
  {
    const int col = lane * 4 + ((lane * 4 >= 16 * (DEG - 1)) ? 16 : 0);
    const bool wr = (lane < 12);
    const float4 z = make_float4(0.f, 0.f, 0.f, 0.f);
    for (int n = w; n < count; n += NWARP){
      const unsigned node = (unsigned)Rs[n * RPG];
      if (wr) *(float4*)&out[(size_t)(node * 64u) + col] = z;
    }
  }

  // ---- Phase 2b: register-tiled GEMM, f32x2 FMA, feature-split across lanes.
  {
    constexpr int NGL = 2 * TK / FS;
    static_assert(NGL == 2, "lane mapping assumes NGL==2");
    const int kg  = lane >> (1 + (FS == 2 ? 1 : 2));
    const int fs  = (lane >> 1) & (FS - 1);
    const int ng  = (w << 1) | (lane & 1);

    unsigned long long acc[TN][TK];
    #pragma unroll
    for (int i = 0; i < TN; i++)
      #pragma unroll
      for (int j = 0; j < TK; j++) acc[i][j] = 0ULL;

    const float* xb = Xs + (ng * TN) * LP + fs * 4;
    const float* wb = Ws + (kg * TK) * LP + fs * 4;
    constexpr int CHUNKS = L / (4 * FS);

    #pragma unroll
    for (int cidx = 0; cidx < CHUNKS; cidx++){
      const int off = cidx * 4 * FS;
      ulonglong2 xv[TN], wv[TK];
      #pragma unroll
      for (int i = 0; i < TN; i++)
        xv[i] = *(const ulonglong2*)(xb + i * LP + off);
      #pragma unroll
      for (int j = 0; j < TK; j++)
        wv[j] = *(const ulonglong2*)(wb + j * LP + off);
      #pragma unroll
      for (int i = 0; i < TN; i++){
        #pragma unroll
        for (int j = 0; j < TK; j++){
          acc[i][j] = ffma2(xv[i].x, wv[j].x, acc[i][j]);
          acc[i][j] = ffma2(xv[i].y, wv[j].y, acc[i][j]);
        }
      }
    }

    // cross-fs reduction (fs lives in lane bits starting at bit 1)
    #pragma unroll
    for (int mask = 2; mask < 2 * FS; mask <<= 1){
      #pragma unroll
      for (int i = 0; i < TN; i++)
        #pragma unroll
        for (int j = 0; j < TK; j++){
          unsigned long long o = __shfl_xor_sync(0xffffffffu, acc[i][j], mask);
          acc[i][j] = fadd2(acc[i][j], o);
        }
    }

    // fs==0 lanes write TK scores per node at col 16*(DEG-1)+kg*TK
    if (fs == 0){
      #pragma unroll
      for (int i = 0; i < TN; i++){
        const int n = ng * TN + i;
        if (n < count){
          const unsigned node = (unsigned)Rs[n * RPG];
          float s[TK];
          #pragma unroll
          for (int j = 0; j < TK; j++){
            const float2 a = unpack2(acc[i][j]);
            s[j] = a.x + a.y;
          }
          float* dst = &out[(size_t)(node * 64u) + (DEG - 1) * 16 + kg * TK];
          if (TK == 4){
            float4 v4; v4.x = s[0]; v4.y = s[1]; v4.z = s[2]; v4.w = s[3];
            *(float4*)dst = v4;
          } else {
            float2 v2; v2.x = s[0]; v2.y = s[1];
            *(float2*)dst = v2;
          }
        }
      }
    }
  }
}

static inline int smem_bytes(int deg){
  const int LP = (1 + deg) * FF + 4;
  const int RTOT = NT * (1 + deg);
  return ((NT + KK) * LP) * (int)sizeof(float) + RTOT * (int)sizeof(int);
}

extern "C" void kernel_launch(void* const* d_in, const int* in_sizes, int n_in,
                              void* d_out, int out_size)
{
  const float* x = (const float*)d_in[0];
  const void *sel[4], *nei[4];
  const float *Wf[4], *Wn[4];
  int Nd[4];

  if (in_sizes[1] == 512){
    // reference-signature order: x, (Wf,Wn)x4, sel1..4, nei1..4
    for (int d = 0; d < 4; d++){
      Wf[d]  = (const float*)d_in[1 + 2 * d];
      Wn[d]  = (const float*)d_in[2 + 2 * d];
      sel[d] = d_in[9 + d];
      nei[d] = d_in[13 + d];
      Nd[d]  = in_sizes[9 + d];
    }
  } else {
    // setup_inputs dict order: x, then (sel, nei, Wf, Wn) per degree
    int b = 1;
    for (int d = 0; d < 4; d++){
      sel[d] = d_in[b + 0];
      nei[d] = d_in[b + 1];
      Wf[d]  = (const float*)d_in[b + 2];
      Wn[d]  = (const float*)d_in[b + 3];
      Nd[d]  = in_sizes[b + 0];
      b += 4;
    }
  }

  float* out = (float*)d_out;

  cudaFuncSetAttribute((const void*)score_kernel<1,4,2,2,4>, cudaFuncAttributeMaxDynamicSharedMemorySize, smem_bytes(1));
  cudaFuncSetAttribute((const void*)score_kernel<2,4,2,2,4>, cudaFuncAttributeMaxDynamicSharedMemorySize, smem_bytes(2));
  cudaFuncSetAttribute((const void*)score_kernel<3,4,4,4,3>, cudaFuncAttributeMaxDynamicSharedMemorySize, smem_bytes(3));
  cudaFuncSetAttribute((const void*)score_kernel<4,4,4,4,3>, cudaFuncAttributeMaxDynamicSharedMemorySize, smem_bytes(4));

  score_kernel<1,4,2,2,4><<<(Nd[0] + NT - 1) / NT, NTHREADS, smem_bytes(1)>>>(
      x, sel[0], nei[0], Wf[0], Wn[0], out, Nd[0]);
  score_kernel<2,4,2,2,4><<<(Nd[1] + NT - 1) / NT, NTHREADS, smem_bytes(2)>>>(
      x, sel[1], nei[1], Wf[1], Wn[1], out, Nd[1]);
  score_kernel<3,4,4,4,3><<<(Nd[2] + NT - 1) / NT, NTHREADS, smem_bytes(3)>>>(
      x, sel[2], nei[2], Wf[2], Wn[2], out, Nd[2]);
  score_kernel<4,4,4,4,3><<<(Nd[3] + NT - 1) / NT, NTHREADS, smem_bytes(4)>>>(
      x, sel[3], nei[3], Wf[3], Wn[3], out, Nd[3]);
}